// round 7
// baseline (speedup 1.0000x reference)
#include <cuda_runtime.h>
#include <cuda_bf16.h>
#include <stdint.h>

#define N_NODES 50000
#define D 256
#define N_EDGES 400000

// Scratch — device globals (no allocations allowed).
__device__ float g_h[(size_t)N_NODES * D];     // GEMM output (per layer)
__device__ float g_agg[(size_t)N_NODES * D];   // layer-1 activations
__device__ float g_dinv[N_NODES];              // 1/sqrt(deg) (deg incl. self-loop)
__device__ int   g_cnt[N_NODES];               // in-edge counts (excl. self-loop)
__device__ int   g_cursor[N_NODES];            // bucket-fill cursors
__device__ int   g_rowstart[N_NODES + 1];      // CSR row offsets (by dst)
__device__ int   g_csr_src[N_EDGES];           // CSR: source node per in-edge
__device__ float g_csr_w[N_EDGES];             // CSR: dinv[src]*dinv[dst] per in-edge
__device__ int   g_src[N_EDGES];               // decoded int32 edge sources
__device__ int   g_dst[N_EDGES];               // decoded int32 edge destinations
__device__ int   g_is64;                       // 1 if edge_index is int64

// ---------------------------------------------------------------------------
// dtype detection + index conversion (edge_index may be int32 or int64)
// ---------------------------------------------------------------------------
__global__ void detect_idx_kernel(const unsigned int* __restrict__ ei32) {
    if (threadIdx.x != 0 || blockIdx.x != 0) return;
    int is64 = 1;
    for (int i = 0; i < 64; i++)
        if (ei32[2 * i + 1] != 0u) { is64 = 0; break; }
    g_is64 = is64;
}

__global__ void convert_idx_kernel(const void* __restrict__ ei, int* __restrict__ srcOut,
                                   int* __restrict__ dstOut) {
    int i = blockIdx.x * blockDim.x + threadIdx.x;
    if (i >= N_EDGES) return;
    if (g_is64) {
        const long long* e = (const long long*)ei;
        srcOut[i] = (int)e[i];
        dstOut[i] = (int)e[i + N_EDGES];
    } else {
        const int* e = (const int*)ei;
        srcOut[i] = e[i];
        dstOut[i] = e[i + N_EDGES];
    }
}

// ---------------------------------------------------------------------------
// CSR build: count -> scan -> dinv -> fill
// ---------------------------------------------------------------------------
__global__ void zero_cnt_kernel(int* cnt, int* cursor) {
    int i = blockIdx.x * blockDim.x + threadIdx.x;
    if (i < N_NODES) { cnt[i] = 0; cursor[i] = 0; }
}

__global__ void count_kernel(const int* __restrict__ dst, int* cnt) {
    int i = blockIdx.x * blockDim.x + threadIdx.x;
    if (i < N_EDGES) atomicAdd(&cnt[dst[i]], 1);
}

// Single-block exclusive prefix scan over 50000 counts (1024 threads).
__global__ __launch_bounds__(1024) void scan_kernel(const int* __restrict__ cnt,
                                                    int* __restrict__ rowstart) {
    __shared__ int sums[1024];
    const int tid = threadIdx.x;
    const int CH = (N_NODES + 1023) / 1024;  // 49
    const int base = tid * CH;
    int s = 0;
    for (int i = 0; i < CH; i++) {
        int idx = base + i;
        if (idx < N_NODES) s += cnt[idx];
    }
    sums[tid] = s;
    __syncthreads();
    for (int off = 1; off < 1024; off <<= 1) {
        int u = (tid >= off) ? sums[tid - off] : 0;
        __syncthreads();
        sums[tid] += u;
        __syncthreads();
    }
    int run = (tid == 0) ? 0 : sums[tid - 1];
    for (int i = 0; i < CH; i++) {
        int idx = base + i;
        if (idx < N_NODES) { rowstart[idx] = run; run += cnt[idx]; }
    }
    if (tid == 1023) rowstart[N_NODES] = sums[1023];
}

__global__ void dinv_kernel(const int* __restrict__ cnt, float* dinv) {
    int i = blockIdx.x * blockDim.x + threadIdx.x;
    if (i < N_NODES) dinv[i] = rsqrtf((float)(cnt[i] + 1));  // +1 self-loop
}

__global__ void fill_kernel(const int* __restrict__ src, const int* __restrict__ dst,
                            const int* __restrict__ rowstart, int* cursor,
                            const float* __restrict__ dinv,
                            int* __restrict__ csr_src, float* __restrict__ csr_w) {
    int i = blockIdx.x * blockDim.x + threadIdx.x;
    if (i >= N_EDGES) return;
    int s = src[i], t = dst[i];
    int pos = rowstart[t] + atomicAdd(&cursor[t], 1);
    csr_src[pos] = s;
    csr_w[pos] = dinv[s] * dinv[t];
}

// ---------------------------------------------------------------------------
// TF32 split-precision tensor-core GEMM (pre-split in SMEM, mask-based split).
// C[M x 256] = A[M x 256] @ B[256 x 256], fp32 in/out, row-major.
// A = Ah + Al (exact; Ah = tf32 bits), C ~= AhBh + AhBl + AlBh.
// Block tile 128x64, 8 warps, warp tile 32x32, mma.sync m16n8k8.
// ---------------------------------------------------------------------------
#define BM 128
#define BN 64
#define BK 16

__device__ __forceinline__ void split2(float x, float& hi, float& lo) {
    hi = __uint_as_float(__float_as_uint(x) & 0xFFFFE000u);  // exact tf32 bits
    lo = x - hi;                                             // exact residual
}

__device__ __forceinline__ void mma_tf32(float* c, const uint32_t* a, const uint32_t* b) {
    asm volatile(
        "mma.sync.aligned.m16n8k8.row.col.f32.tf32.tf32.f32 "
        "{%0,%1,%2,%3}, {%4,%5,%6,%7}, {%8,%9}, {%0,%1,%2,%3};"
        : "+f"(c[0]), "+f"(c[1]), "+f"(c[2]), "+f"(c[3])
        : "r"(a[0]), "r"(a[1]), "r"(a[2]), "r"(a[3]), "r"(b[0]), "r"(b[1]));
}

__global__ __launch_bounds__(256) void tgemm_kernel(
    const float* __restrict__ A, const float* __restrict__ B,
    float* __restrict__ C, int M) {
    __shared__ float As_hi[BK][BM + 4], As_lo[BK][BM + 4];
    __shared__ float Bs_hi[BK][BN + 4], Bs_lo[BK][BN + 4];

    const int tid = threadIdx.x;
    const int lane = tid & 31;
    const int wid = tid >> 5;
    const int warpM = wid & 3;
    const int warpN = wid >> 2;
    const int g = lane >> 2;
    const int t = lane & 3;
    const int rowBase = blockIdx.x * BM;
    const int colBase = blockIdx.y * BN;

    // per-thread tile-load indices
    const int q0 = tid * 2, q1 = tid * 2 + 1;
    const int ar0 = q0 >> 2, ak0 = (q0 & 3) << 2;
    const int ar1 = q1 >> 2, ak1 = (q1 & 3) << 2;
    const int br = tid >> 4;
    const int bc = (tid & 15) << 2;
    const int grow0 = rowBase + ar0;
    const int grow1 = rowBase + ar1;

    float c[2][4][4];
#pragma unroll
    for (int mt = 0; mt < 2; mt++)
#pragma unroll
        for (int nt = 0; nt < 4; nt++)
#pragma unroll
            for (int r = 0; r < 4; r++) c[mt][nt][r] = 0.0f;

    // prefetch tile k0=0 into registers
    float4 pa0 = make_float4(0.f, 0.f, 0.f, 0.f);
    float4 pa1 = make_float4(0.f, 0.f, 0.f, 0.f);
    if (grow0 < M) pa0 = *(const float4*)(A + (size_t)grow0 * D + ak0);
    if (grow1 < M) pa1 = *(const float4*)(A + (size_t)grow1 * D + ak1);
    float4 pb = *(const float4*)(B + (size_t)br * D + colBase + bc);

    for (int k0 = 0; k0 < D; k0 += BK) {
        // split + store current tile to SMEM
        {
            float h0, l0;
            split2(pa0.x, h0, l0); As_hi[ak0 + 0][ar0] = h0; As_lo[ak0 + 0][ar0] = l0;
            split2(pa0.y, h0, l0); As_hi[ak0 + 1][ar0] = h0; As_lo[ak0 + 1][ar0] = l0;
            split2(pa0.z, h0, l0); As_hi[ak0 + 2][ar0] = h0; As_lo[ak0 + 2][ar0] = l0;
            split2(pa0.w, h0, l0); As_hi[ak0 + 3][ar0] = h0; As_lo[ak0 + 3][ar0] = l0;
            split2(pa1.x, h0, l0); As_hi[ak1 + 0][ar1] = h0; As_lo[ak1 + 0][ar1] = l0;
            split2(pa1.y, h0, l0); As_hi[ak1 + 1][ar1] = h0; As_lo[ak1 + 1][ar1] = l0;
            split2(pa1.z, h0, l0); As_hi[ak1 + 2][ar1] = h0; As_lo[ak1 + 2][ar1] = l0;
            split2(pa1.w, h0, l0); As_hi[ak1 + 3][ar1] = h0; As_lo[ak1 + 3][ar1] = l0;
            split2(pb.x, h0, l0); Bs_hi[br][bc + 0] = h0; Bs_lo[br][bc + 0] = l0;
            split2(pb.y, h0, l0); Bs_hi[br][bc + 1] = h0; Bs_lo[br][bc + 1] = l0;
            split2(pb.z, h0, l0); Bs_hi[br][bc + 2] = h0; Bs_lo[br][bc + 2] = l0;
            split2(pb.w, h0, l0); Bs_hi[br][bc + 3] = h0; Bs_lo[br][bc + 3] = l0;
        }
        __syncthreads();

        // prefetch next tile while computing this one
        if (k0 + BK < D) {
            int kn = k0 + BK;
            if (grow0 < M) pa0 = *(const float4*)(A + (size_t)grow0 * D + kn + ak0);
            if (grow1 < M) pa1 = *(const float4*)(A + (size_t)grow1 * D + kn + ak1);
            pb = *(const float4*)(B + (size_t)(kn + br) * D + colBase + bc);
        }

#pragma unroll
        for (int ks = 0; ks < BK; ks += 8) {
            uint32_t ah[2][4], al[2][4];
#pragma unroll
            for (int mt = 0; mt < 2; mt++) {
                int m0 = warpM * 32 + mt * 16;
                ah[mt][0] = __float_as_uint(As_hi[ks + t][m0 + g]);
                al[mt][0] = __float_as_uint(As_lo[ks + t][m0 + g]);
                ah[mt][1] = __float_as_uint(As_hi[ks + t][m0 + g + 8]);
                al[mt][1] = __float_as_uint(As_lo[ks + t][m0 + g + 8]);
                ah[mt][2] = __float_as_uint(As_hi[ks + t + 4][m0 + g]);
                al[mt][2] = __float_as_uint(As_lo[ks + t + 4][m0 + g]);
                ah[mt][3] = __float_as_uint(As_hi[ks + t + 4][m0 + g + 8]);
                al[mt][3] = __float_as_uint(As_lo[ks + t + 4][m0 + g + 8]);
            }
            uint32_t bh[4][2], bl[4][2];
#pragma unroll
            for (int nt = 0; nt < 4; nt++) {
                int n0 = warpN * 32 + nt * 8;
                bh[nt][0] = __float_as_uint(Bs_hi[ks + t][n0 + g]);
                bl[nt][0] = __float_as_uint(Bs_lo[ks + t][n0 + g]);
                bh[nt][1] = __float_as_uint(Bs_hi[ks + t + 4][n0 + g]);
                bl[nt][1] = __float_as_uint(Bs_lo[ks + t + 4][n0 + g]);
            }
#pragma unroll
            for (int mt = 0; mt < 2; mt++)
#pragma unroll
                for (int nt = 0; nt < 4; nt++) {
                    mma_tf32(c[mt][nt], ah[mt], bh[nt]);
                    mma_tf32(c[mt][nt], ah[mt], bl[nt]);
                    mma_tf32(c[mt][nt], al[mt], bh[nt]);
                }
        }
        __syncthreads();
    }

    // Epilogue
#pragma unroll
    for (int mt = 0; mt < 2; mt++) {
#pragma unroll
        for (int nt = 0; nt < 4; nt++) {
            int row0 = rowBase + warpM * 32 + mt * 16 + g;
            int col = colBase + warpN * 32 + nt * 8 + t * 2;
            if (row0 < M)
                *(float2*)(C + (size_t)row0 * D + col) =
                    make_float2(c[mt][nt][0], c[mt][nt][1]);
            if (row0 + 8 < M)
                *(float2*)(C + (size_t)(row0 + 8) * D + col) =
                    make_float2(c[mt][nt][2], c[mt][nt][3]);
        }
    }
}

// ---------------------------------------------------------------------------
// Fused gather: warp-per-node.
// out[n,:] = relu( h[n,:]*dinv[n]^2 + sum_in-edges h[src,:]*w + b )
// ---------------------------------------------------------------------------
__global__ __launch_bounds__(256) void gather_kernel(
    const float* __restrict__ h,
    const int* __restrict__ rowstart,
    const int* __restrict__ csr_src,
    const float* __restrict__ csr_w,
    const float* __restrict__ dinv,
    const float* __restrict__ bias,
    float* __restrict__ out) {
    int node = (blockIdx.x * blockDim.x + threadIdx.x) >> 5;
    if (node >= N_NODES) return;
    int lane = threadIdx.x & 31;

    float dv = dinv[node];
    float w0 = dv * dv;
    const float4* selfp = (const float4*)(h + (size_t)node * D);
    float4 a0 = selfp[lane];
    float4 a1 = selfp[lane + 32];
    a0.x *= w0; a0.y *= w0; a0.z *= w0; a0.w *= w0;
    a1.x *= w0; a1.y *= w0; a1.z *= w0; a1.w *= w0;

    int beg = rowstart[node];
    int end = rowstart[node + 1];
    for (int j = beg; j < end; j++) {
        int s = __ldg(&csr_src[j]);
        float w = __ldg(&csr_w[j]);
        const float4* sp = (const float4*)(h + (size_t)s * D);
        float4 v0 = sp[lane];
        float4 v1 = sp[lane + 32];
        a0.x = fmaf(v0.x, w, a0.x); a0.y = fmaf(v0.y, w, a0.y);
        a0.z = fmaf(v0.z, w, a0.z); a0.w = fmaf(v0.w, w, a0.w);
        a1.x = fmaf(v1.x, w, a1.x); a1.y = fmaf(v1.y, w, a1.y);
        a1.z = fmaf(v1.z, w, a1.z); a1.w = fmaf(v1.w, w, a1.w);
    }

    const float4* b4 = (const float4*)bias;
    float4 bb0 = b4[lane];
    float4 bb1 = b4[lane + 32];
    a0.x = fmaxf(a0.x + bb0.x, 0.f); a0.y = fmaxf(a0.y + bb0.y, 0.f);
    a0.z = fmaxf(a0.z + bb0.z, 0.f); a0.w = fmaxf(a0.w + bb0.w, 0.f);
    a1.x = fmaxf(a1.x + bb1.x, 0.f); a1.y = fmaxf(a1.y + bb1.y, 0.f);
    a1.z = fmaxf(a1.z + bb1.z, 0.f); a1.w = fmaxf(a1.w + bb1.w, 0.f);

    float4* op = (float4*)(out + (size_t)node * D);
    op[lane] = a0;
    op[lane + 32] = a1;
}

// ---------------------------------------------------------------------------
// Launch
// ---------------------------------------------------------------------------
extern "C" void kernel_launch(void* const* d_in, const int* in_sizes, int n_in,
                              void* d_out, int out_size) {
    const float* x = (const float*)d_in[0];
    const void* ei = d_in[1];  // [2, E] — int32 or int64, detected on device
    const float* W1 = (const float*)d_in[2];
    const float* b1 = (const float*)d_in[3];
    const float* W2 = (const float*)d_in[4];
    const float* b2 = (const float*)d_in[5];
    float* out = (float*)d_out;

    float *h, *agg, *dinv, *csr_w;
    int *srcI, *dstI, *cnt, *cursor, *rowstart, *csr_src;
    cudaGetSymbolAddress((void**)&h, g_h);
    cudaGetSymbolAddress((void**)&agg, g_agg);
    cudaGetSymbolAddress((void**)&dinv, g_dinv);
    cudaGetSymbolAddress((void**)&cnt, g_cnt);
    cudaGetSymbolAddress((void**)&cursor, g_cursor);
    cudaGetSymbolAddress((void**)&rowstart, g_rowstart);
    cudaGetSymbolAddress((void**)&csr_src, g_csr_src);
    cudaGetSymbolAddress((void**)&csr_w, g_csr_w);
    cudaGetSymbolAddress((void**)&srcI, g_src);
    cudaGetSymbolAddress((void**)&dstI, g_dst);

    const int TPB = 256;
    const int gN = (N_NODES + TPB - 1) / TPB;
    const int gE = (N_EDGES + TPB - 1) / TPB;
    const int gGather = (int)(((long long)N_NODES * 32 + TPB - 1) / TPB);
    dim3 gGemm((N_NODES + BM - 1) / BM, D / BN);

    // ---- prep: decode indices, build CSR by destination ----
    detect_idx_kernel<<<1, 32>>>((const unsigned int*)ei);
    convert_idx_kernel<<<gE, TPB>>>(ei, srcI, dstI);
    zero_cnt_kernel<<<gN, TPB>>>(cnt, cursor);
    count_kernel<<<gE, TPB>>>(dstI, cnt);
    scan_kernel<<<1, 1024>>>(cnt, rowstart);
    dinv_kernel<<<gN, TPB>>>(cnt, dinv);
    fill_kernel<<<gE, TPB>>>(srcI, dstI, rowstart, cursor, dinv, csr_src, csr_w);

    // ---- layer 1 ----
    tgemm_kernel<<<gGemm, TPB>>>(x, W1, h, N_NODES);
    gather_kernel<<<gGather, TPB>>>(h, rowstart, csr_src, csr_w, dinv, b1, agg);

    // ---- layer 2 ----
    tgemm_kernel<<<gGemm, TPB>>>(agg, W2, h, N_NODES);
    gather_kernel<<<gGather, TPB>>>(h, rowstart, csr_src, csr_w, dinv, b2, out);
}

// round 9
// speedup vs baseline: 1.1516x; 1.1516x over previous
#include <cuda_runtime.h>
#include <cuda_bf16.h>
#include <stdint.h>

#define N_NODES 50000
#define D 256
#define N_EDGES 400000
#define KP (D / 2)          // 128 packed k-pair words per row

// Scratch — device globals (no allocations allowed).
__device__ float    g_h[(size_t)N_NODES * D];    // GEMM output (per layer)
__device__ float    g_agg[(size_t)N_NODES * D];  // layer-1 activations
__device__ uint32_t g_ah[(size_t)N_NODES * KP];  // packed bf16x2 hi of A (x / agg)
__device__ uint32_t g_al[(size_t)N_NODES * KP];  // packed bf16x2 lo of A
__device__ uint32_t g_w1h[(size_t)KP * D], g_w1l[(size_t)KP * D];  // W1 split [k2][n]
__device__ uint32_t g_w2h[(size_t)KP * D], g_w2l[(size_t)KP * D];  // W2 split [k2][n]
__device__ float    g_dinv[N_NODES];
__device__ int      g_cnt[N_NODES];
__device__ int      g_cursor[N_NODES];
__device__ int      g_rowstart[N_NODES + 1];
__device__ int      g_csr_src[N_EDGES];
__device__ float    g_csr_w[N_EDGES];
__device__ int      g_src[N_EDGES];
__device__ int      g_dst[N_EDGES];
__device__ int      g_is64;

// ---------------------------------------------------------------------------
// dtype detection + index conversion
// ---------------------------------------------------------------------------
__global__ void detect_idx_kernel(const unsigned int* __restrict__ ei32) {
    if (threadIdx.x != 0 || blockIdx.x != 0) return;
    int is64 = 1;
    for (int i = 0; i < 64; i++)
        if (ei32[2 * i + 1] != 0u) { is64 = 0; break; }
    g_is64 = is64;
}

__global__ void convert_idx_kernel(const void* __restrict__ ei, int* __restrict__ srcOut,
                                   int* __restrict__ dstOut) {
    int i = blockIdx.x * blockDim.x + threadIdx.x;
    if (i >= N_EDGES) return;
    if (g_is64) {
        const long long* e = (const long long*)ei;
        srcOut[i] = (int)e[i];
        dstOut[i] = (int)e[i + N_EDGES];
    } else {
        const int* e = (const int*)ei;
        srcOut[i] = e[i];
        dstOut[i] = e[i + N_EDGES];
    }
}

// ---------------------------------------------------------------------------
// CSR build
// ---------------------------------------------------------------------------
__global__ void zero_cnt_kernel(int* cnt, int* cursor) {
    int i = blockIdx.x * blockDim.x + threadIdx.x;
    if (i < N_NODES) { cnt[i] = 0; cursor[i] = 0; }
}

__global__ void count_kernel(const int* __restrict__ dst, int* cnt) {
    int i = blockIdx.x * blockDim.x + threadIdx.x;
    if (i < N_EDGES) atomicAdd(&cnt[dst[i]], 1);
}

__global__ __launch_bounds__(1024) void scan_kernel(const int* __restrict__ cnt,
                                                    int* __restrict__ rowstart) {
    __shared__ int sums[1024];
    const int tid = threadIdx.x;
    const int CH = (N_NODES + 1023) / 1024;
    const int base = tid * CH;
    int s = 0;
    for (int i = 0; i < CH; i++) {
        int idx = base + i;
        if (idx < N_NODES) s += cnt[idx];
    }
    sums[tid] = s;
    __syncthreads();
    for (int off = 1; off < 1024; off <<= 1) {
        int u = (tid >= off) ? sums[tid - off] : 0;
        __syncthreads();
        sums[tid] += u;
        __syncthreads();
    }
    int run = (tid == 0) ? 0 : sums[tid - 1];
    for (int i = 0; i < CH; i++) {
        int idx = base + i;
        if (idx < N_NODES) { rowstart[idx] = run; run += cnt[idx]; }
    }
    if (tid == 1023) rowstart[N_NODES] = sums[1023];
}

__global__ void dinv_kernel(const int* __restrict__ cnt, float* dinv) {
    int i = blockIdx.x * blockDim.x + threadIdx.x;
    if (i < N_NODES) dinv[i] = rsqrtf((float)(cnt[i] + 1));
}

__global__ void fill_kernel(const int* __restrict__ src, const int* __restrict__ dst,
                            const int* __restrict__ rowstart, int* cursor,
                            const float* __restrict__ dinv,
                            int* __restrict__ csr_src, float* __restrict__ csr_w) {
    int i = blockIdx.x * blockDim.x + threadIdx.x;
    if (i >= N_EDGES) return;
    int s = src[i], t = dst[i];
    int pos = rowstart[t] + atomicAdd(&cursor[t], 1);
    csr_src[pos] = s;
    csr_w[pos] = dinv[s] * dinv[t];
}

// ---------------------------------------------------------------------------
// bf16 split + pack, row-major k-pairs: in fp32 [R][256] -> hi/lo u32 [R][128]
// word i holds (bf16(x[2k2]), bf16(x[2k2+1])) with even k in low 16 bits.
// ---------------------------------------------------------------------------
__global__ void split_rowmajor_kernel(const float* __restrict__ in,
                                      uint32_t* __restrict__ hi, uint32_t* __restrict__ lo,
                                      int nPairs) {
    int i = blockIdx.x * blockDim.x + threadIdx.x;
    if (i >= nPairs) return;
    float2 v = ((const float2*)in)[i];
    __nv_bfloat162 h2 = __floats2bfloat162_rn(v.x, v.y);
    float r0 = v.x - __bfloat162float(h2.x);
    float r1 = v.y - __bfloat162float(h2.y);
    __nv_bfloat162 l2 = __floats2bfloat162_rn(r0, r1);
    hi[i] = *(uint32_t*)&h2;
    lo[i] = *(uint32_t*)&l2;
}

// W split, k-pair packed column layout: fp32 [256(k)][256(n)] ->
// u32 [128(k2)][256(n)]: out[k2][n] = pack(bf16(W[2k2][n]), bf16(W[2k2+1][n]))
__global__ void split_w_kernel(const float* __restrict__ W,
                               uint32_t* __restrict__ hi, uint32_t* __restrict__ lo) {
    int i = blockIdx.x * blockDim.x + threadIdx.x;  // over 128*256
    if (i >= KP * D) return;
    int k2 = i >> 8;         // 0..127
    int n = i & 255;
    float x0 = W[(size_t)(2 * k2) * D + n];
    float x1 = W[(size_t)(2 * k2 + 1) * D + n];
    __nv_bfloat162 h2 = __floats2bfloat162_rn(x0, x1);
    float r0 = x0 - __bfloat162float(h2.x);
    float r1 = x1 - __bfloat162float(h2.y);
    __nv_bfloat162 l2 = __floats2bfloat162_rn(r0, r1);
    hi[i] = *(uint32_t*)&h2;
    lo[i] = *(uint32_t*)&l2;
}

// ---------------------------------------------------------------------------
// bf16 split tensor-core GEMM: C = Ah@Bh + Ah@Bl + Al@Bh  (fp32 accum)
// Block 128x64, 8 warps (warp tile 32x32), mma.sync m16n8k16.bf16.
// A packed [row][k2] u32; B packed [k2][n] u32. 24 iterations = 3 phases x 8 tiles.
// ---------------------------------------------------------------------------
#define BM 128
#define BN 64
#define KW 16   // k2 words per tile (=32 k values)
#define ASTRIDE (KW + 4)   // 20 words: conflict-free, uint4-alignable
#define BSTRIDE (BN + 8)   // 72 words: conflict-free, uint4-alignable

__device__ __forceinline__ void mma_bf16(float* c, const uint32_t* a, const uint32_t* b) {
    asm volatile(
        "mma.sync.aligned.m16n8k16.row.col.f32.bf16.bf16.f32 "
        "{%0,%1,%2,%3}, {%4,%5,%6,%7}, {%8,%9}, {%0,%1,%2,%3};"
        : "+f"(c[0]), "+f"(c[1]), "+f"(c[2]), "+f"(c[3])
        : "r"(a[0]), "r"(a[1]), "r"(a[2]), "r"(a[3]), "r"(b[0]), "r"(b[1]));
}

__global__ __launch_bounds__(256) void bgemm_kernel(
    const uint32_t* __restrict__ Ah, const uint32_t* __restrict__ Al,
    const uint32_t* __restrict__ Bh, const uint32_t* __restrict__ Bl,
    float* __restrict__ C, int M) {
    __shared__ uint32_t As2[BM * ASTRIDE];
    __shared__ uint32_t Bs2[KW * BSTRIDE];

    const int tid = threadIdx.x;
    const int lane = tid & 31;
    const int wid = tid >> 5;
    const int warpM = wid & 3;
    const int warpN = wid >> 2;
    const int g = lane >> 2;
    const int t = lane & 3;
    const int rowBase = blockIdx.x * BM;
    const int colBase = blockIdx.y * BN;

    // A loader: 128 rows x 16 words = 512 uint4, 2/thread
    const int q0 = tid * 2, q1 = q0 + 1;
    const int ar0 = q0 >> 2, aw0 = (q0 & 3) << 2;
    const int ar1 = q1 >> 2, aw1 = (q1 & 3) << 2;
    const int grow0 = rowBase + ar0, grow1 = rowBase + ar1;
    // B loader: 16 rows x 64 words = 256 uint4, 1/thread
    const int br = tid >> 4, bw = (tid & 15) << 2;

    const uint32_t* APtrs[3] = {Ah, Ah, Al};
    const uint32_t* BPtrs[3] = {Bh, Bl, Bh};

    float c[2][4][4];
#pragma unroll
    for (int mt = 0; mt < 2; mt++)
#pragma unroll
        for (int nt = 0; nt < 4; nt++)
#pragma unroll
            for (int r = 0; r < 4; r++) c[mt][nt][r] = 0.0f;

    uint4 pa0, pa1, pb;
    {   // prefetch iteration 0 (phase 0, kw0 = 0)
        const uint32_t* Ap = APtrs[0];
        const uint32_t* Bp = BPtrs[0];
        pa0 = (grow0 < M) ? *(const uint4*)(Ap + (size_t)grow0 * KP + aw0)
                          : make_uint4(0, 0, 0, 0);
        pa1 = (grow1 < M) ? *(const uint4*)(Ap + (size_t)grow1 * KP + aw1)
                          : make_uint4(0, 0, 0, 0);
        pb = *(const uint4*)(Bp + (size_t)br * D + colBase + bw);
    }

    for (int it = 0; it < 24; it++) {
        *(uint4*)&As2[ar0 * ASTRIDE + aw0] = pa0;
        *(uint4*)&As2[ar1 * ASTRIDE + aw1] = pa1;
        *(uint4*)&Bs2[br * BSTRIDE + bw] = pb;
        __syncthreads();

        if (it + 1 < 24) {
            int nx = it + 1;
            int p = nx >> 3;
            int kw0 = (nx & 7) * KW;
            const uint32_t* Ap = APtrs[p];
            const uint32_t* Bp = BPtrs[p];
            pa0 = (grow0 < M) ? *(const uint4*)(Ap + (size_t)grow0 * KP + kw0 + aw0)
                              : make_uint4(0, 0, 0, 0);
            pa1 = (grow1 < M) ? *(const uint4*)(Ap + (size_t)grow1 * KP + kw0 + aw1)
                              : make_uint4(0, 0, 0, 0);
            pb = *(const uint4*)(Bp + (size_t)(kw0 + br) * D + colBase + bw);
        }

#pragma unroll
        for (int ks = 0; ks < 2; ks++) {
            const int kb = ks * 8;     // k2 base within tile
            uint32_t a[2][4], b[4][2];
#pragma unroll
            for (int mt = 0; mt < 2; mt++) {
                int m0 = warpM * 32 + mt * 16;
                a[mt][0] = As2[(m0 + g) * ASTRIDE + kb + t];
                a[mt][1] = As2[(m0 + g + 8) * ASTRIDE + kb + t];
                a[mt][2] = As2[(m0 + g) * ASTRIDE + kb + t + 4];
                a[mt][3] = As2[(m0 + g + 8) * ASTRIDE + kb + t + 4];
            }
#pragma unroll
            for (int nt = 0; nt < 4; nt++) {
                int n0 = warpN * 32 + nt * 8;
                b[nt][0] = Bs2[(kb + t) * BSTRIDE + n0 + g];
                b[nt][1] = Bs2[(kb + t + 4) * BSTRIDE + n0 + g];
            }
#pragma unroll
            for (int mt = 0; mt < 2; mt++)
#pragma unroll
                for (int nt = 0; nt < 4; nt++)
                    mma_bf16(c[mt][nt], a[mt], b[nt]);
        }
        __syncthreads();
    }

    // Epilogue
#pragma unroll
    for (int mt = 0; mt < 2; mt++) {
#pragma unroll
        for (int nt = 0; nt < 4; nt++) {
            int row0 = rowBase + warpM * 32 + mt * 16 + g;
            int col = colBase + warpN * 32 + nt * 8 + t * 2;
            if (row0 < M)
                *(float2*)(C + (size_t)row0 * D + col) =
                    make_float2(c[mt][nt][0], c[mt][nt][1]);
            if (row0 + 8 < M)
                *(float2*)(C + (size_t)(row0 + 8) * D + col) =
                    make_float2(c[mt][nt][2], c[mt][nt][3]);
        }
    }
}

// ---------------------------------------------------------------------------
// Fused gather: warp-per-node.
// out[n,:] = relu( h[n,:]*dinv[n]^2 + sum_in-edges h[src,:]*w + b )
// ---------------------------------------------------------------------------
__global__ __launch_bounds__(256) void gather_kernel(
    const float* __restrict__ h,
    const int* __restrict__ rowstart,
    const int* __restrict__ csr_src,
    const float* __restrict__ csr_w,
    const float* __restrict__ dinv,
    const float* __restrict__ bias,
    float* __restrict__ out) {
    int node = (blockIdx.x * blockDim.x + threadIdx.x) >> 5;
    if (node >= N_NODES) return;
    int lane = threadIdx.x & 31;

    float dv = dinv[node];
    float w0 = dv * dv;
    const float4* selfp = (const float4*)(h + (size_t)node * D);
    float4 a0 = selfp[lane];
    float4 a1 = selfp[lane + 32];
    a0.x *= w0; a0.y *= w0; a0.z *= w0; a0.w *= w0;
    a1.x *= w0; a1.y *= w0; a1.z *= w0; a1.w *= w0;

    int beg = rowstart[node];
    int end = rowstart[node + 1];
    for (int j = beg; j < end; j++) {
        int s = __ldg(&csr_src[j]);
        float w = __ldg(&csr_w[j]);
        const float4* sp = (const float4*)(h + (size_t)s * D);
        float4 v0 = sp[lane];
        float4 v1 = sp[lane + 32];
        a0.x = fmaf(v0.x, w, a0.x); a0.y = fmaf(v0.y, w, a0.y);
        a0.z = fmaf(v0.z, w, a0.z); a0.w = fmaf(v0.w, w, a0.w);
        a1.x = fmaf(v1.x, w, a1.x); a1.y = fmaf(v1.y, w, a1.y);
        a1.z = fmaf(v1.z, w, a1.z); a1.w = fmaf(v1.w, w, a1.w);
    }

    const float4* b4 = (const float4*)bias;
    float4 bb0 = b4[lane];
    float4 bb1 = b4[lane + 32];
    a0.x = fmaxf(a0.x + bb0.x, 0.f); a0.y = fmaxf(a0.y + bb0.y, 0.f);
    a0.z = fmaxf(a0.z + bb0.z, 0.f); a0.w = fmaxf(a0.w + bb0.w, 0.f);
    a1.x = fmaxf(a1.x + bb1.x, 0.f); a1.y = fmaxf(a1.y + bb1.y, 0.f);
    a1.z = fmaxf(a1.z + bb1.z, 0.f); a1.w = fmaxf(a1.w + bb1.w, 0.f);

    float4* op = (float4*)(out + (size_t)node * D);
    op[lane] = a0;
    op[lane + 32] = a1;
}

// ---------------------------------------------------------------------------
// Launch
// ---------------------------------------------------------------------------
extern "C" void kernel_launch(void* const* d_in, const int* in_sizes, int n_in,
                              void* d_out, int out_size) {
    const float* x = (const float*)d_in[0];
    const void* ei = d_in[1];
    const float* W1 = (const float*)d_in[2];
    const float* b1 = (const float*)d_in[3];
    const float* W2 = (const float*)d_in[4];
    const float* b2 = (const float*)d_in[5];
    float* out = (float*)d_out;

    float *h, *agg, *dinv, *csr_w;
    int *srcI, *dstI, *cnt, *cursor, *rowstart, *csr_src;
    uint32_t *ah, *al, *w1h, *w1l, *w2h, *w2l;
    cudaGetSymbolAddress((void**)&h, g_h);
    cudaGetSymbolAddress((void**)&agg, g_agg);
    cudaGetSymbolAddress((void**)&dinv, g_dinv);
    cudaGetSymbolAddress((void**)&cnt, g_cnt);
    cudaGetSymbolAddress((void**)&cursor, g_cursor);
    cudaGetSymbolAddress((void**)&rowstart, g_rowstart);
    cudaGetSymbolAddress((void**)&csr_src, g_csr_src);
    cudaGetSymbolAddress((void**)&csr_w, g_csr_w);
    cudaGetSymbolAddress((void**)&srcI, g_src);
    cudaGetSymbolAddress((void**)&dstI, g_dst);
    cudaGetSymbolAddress((void**)&ah, g_ah);
    cudaGetSymbolAddress((void**)&al, g_al);
    cudaGetSymbolAddress((void**)&w1h, g_w1h);
    cudaGetSymbolAddress((void**)&w1l, g_w1l);
    cudaGetSymbolAddress((void**)&w2h, g_w2h);
    cudaGetSymbolAddress((void**)&w2l, g_w2l);

    const int TPB = 256;
    const int gN = (N_NODES + TPB - 1) / TPB;
    const int gE = (N_EDGES + TPB - 1) / TPB;
    const int gGather = (int)(((long long)N_NODES * 32 + TPB - 1) / TPB);
    const int nPairsA = N_NODES * KP;                 // 6.4M
    const int gSplitA = (nPairsA + TPB - 1) / TPB;
    const int gSplitW = (KP * D + TPB - 1) / TPB;
    dim3 gGemm((N_NODES + BM - 1) / BM, D / BN);

    // ---- prep: decode indices, CSR, weight/input splits ----
    detect_idx_kernel<<<1, 32>>>((const unsigned int*)ei);
    convert_idx_kernel<<<gE, TPB>>>(ei, srcI, dstI);
    zero_cnt_kernel<<<gN, TPB>>>(cnt, cursor);
    count_kernel<<<gE, TPB>>>(dstI, cnt);
    scan_kernel<<<1, 1024>>>(cnt, rowstart);
    dinv_kernel<<<gN, TPB>>>(cnt, dinv);
    fill_kernel<<<gE, TPB>>>(srcI, dstI, rowstart, cursor, dinv, csr_src, csr_w);
    split_w_kernel<<<gSplitW, TPB>>>(W1, w1h, w1l);
    split_w_kernel<<<gSplitW, TPB>>>(W2, w2h, w2l);
    split_rowmajor_kernel<<<gSplitA, TPB>>>(x, ah, al, nPairsA);

    // ---- layer 1 ----
    bgemm_kernel<<<gGemm, TPB>>>(ah, al, w1h, w1l, h, N_NODES);
    gather_kernel<<<gGather, TPB>>>(h, rowstart, csr_src, csr_w, dinv, b1, agg);

    // ---- layer 2 ----
    split_rowmajor_kernel<<<gSplitA, TPB>>>(agg, ah, al, nPairsA);
    bgemm_kernel<<<gGemm, TPB>>>(ah, al, w2h, w2l, h, N_NODES);
    gather_kernel<<<gGather, TPB>>>(h, rowstart, csr_src, csr_w, dinv, b2, out);
}

// round 13
// speedup vs baseline: 1.3937x; 1.2102x over previous
#include <cuda_runtime.h>
#include <cuda_bf16.h>
#include <stdint.h>

#define N_NODES 50000
#define D 256
#define N_EDGES 400000
#define KP (D / 2)          // 128 packed k-pair words per row

// Scratch — device globals (no allocations allowed).
__device__ float    g_h[(size_t)N_NODES * D];    // GEMM output (per layer)
__device__ uint32_t g_ah[(size_t)N_NODES * KP];  // packed bf16x2 hi of A (x / layer-1 act)
__device__ uint32_t g_al[(size_t)N_NODES * KP];  // packed bf16x2 lo of A
__device__ uint32_t g_w1h[(size_t)KP * D], g_w1l[(size_t)KP * D];  // W1 split [k2][n]
__device__ uint32_t g_w2h[(size_t)KP * D], g_w2l[(size_t)KP * D];  // W2 split [k2][n]
__device__ float    g_dinv[N_NODES];
__device__ int      g_cnt[N_NODES];
__device__ int      g_cursor[N_NODES];
__device__ int      g_rowstart[N_NODES + 1];
__device__ int      g_csr_src[N_EDGES];
__device__ float    g_csr_w[N_EDGES];
__device__ int      g_src[N_EDGES];
__device__ int      g_dst[N_EDGES];
__device__ int      g_is64;

// ---------------------------------------------------------------------------
// dtype detection + index conversion
// ---------------------------------------------------------------------------
__global__ void detect_idx_kernel(const unsigned int* __restrict__ ei32) {
    if (threadIdx.x != 0 || blockIdx.x != 0) return;
    int is64 = 1;
    for (int i = 0; i < 64; i++)
        if (ei32[2 * i + 1] != 0u) { is64 = 0; break; }
    g_is64 = is64;
}

__global__ void convert_idx_kernel(const void* __restrict__ ei, int* __restrict__ srcOut,
                                   int* __restrict__ dstOut) {
    int i = blockIdx.x * blockDim.x + threadIdx.x;
    if (i >= N_EDGES) return;
    if (g_is64) {
        const long long* e = (const long long*)ei;
        srcOut[i] = (int)e[i];
        dstOut[i] = (int)e[i + N_EDGES];
    } else {
        const int* e = (const int*)ei;
        srcOut[i] = e[i];
        dstOut[i] = e[i + N_EDGES];
    }
}

// ---------------------------------------------------------------------------
// CSR build
// ---------------------------------------------------------------------------
__global__ void zero_cnt_kernel(int* cnt, int* cursor) {
    int i = blockIdx.x * blockDim.x + threadIdx.x;
    if (i < N_NODES) { cnt[i] = 0; cursor[i] = 0; }
}

__global__ void count_kernel(const int* __restrict__ dst, int* cnt) {
    int i = blockIdx.x * blockDim.x + threadIdx.x;
    if (i < N_EDGES) atomicAdd(&cnt[dst[i]], 1);
}

__global__ __launch_bounds__(1024) void scan_kernel(const int* __restrict__ cnt,
                                                    int* __restrict__ rowstart) {
    __shared__ int sums[1024];
    const int tid = threadIdx.x;
    const int CH = (N_NODES + 1023) / 1024;
    const int base = tid * CH;
    int s = 0;
    for (int i = 0; i < CH; i++) {
        int idx = base + i;
        if (idx < N_NODES) s += cnt[idx];
    }
    sums[tid] = s;
    __syncthreads();
    for (int off = 1; off < 1024; off <<= 1) {
        int u = (tid >= off) ? sums[tid - off] : 0;
        __syncthreads();
        sums[tid] += u;
        __syncthreads();
    }
    int run = (tid == 0) ? 0 : sums[tid - 1];
    for (int i = 0; i < CH; i++) {
        int idx = base + i;
        if (idx < N_NODES) { rowstart[idx] = run; run += cnt[idx]; }
    }
    if (tid == 1023) rowstart[N_NODES] = sums[1023];
}

__global__ void dinv_kernel(const int* __restrict__ cnt, float* dinv) {
    int i = blockIdx.x * blockDim.x + threadIdx.x;
    if (i < N_NODES) dinv[i] = rsqrtf((float)(cnt[i] + 1));
}

__global__ void fill_kernel(const int* __restrict__ src, const int* __restrict__ dst,
                            const int* __restrict__ rowstart, int* cursor,
                            const float* __restrict__ dinv,
                            int* __restrict__ csr_src, float* __restrict__ csr_w) {
    int i = blockIdx.x * blockDim.x + threadIdx.x;
    if (i >= N_EDGES) return;
    int s = src[i], t = dst[i];
    int pos = rowstart[t] + atomicAdd(&cursor[t], 1);
    csr_src[pos] = s;
    csr_w[pos] = dinv[s] * dinv[t];
}

// ---------------------------------------------------------------------------
// bf16 split + pack helpers
// ---------------------------------------------------------------------------
__global__ void split_rowmajor_kernel(const float* __restrict__ in,
                                      uint32_t* __restrict__ hi, uint32_t* __restrict__ lo,
                                      int nPairs) {
    int i = blockIdx.x * blockDim.x + threadIdx.x;
    if (i >= nPairs) return;
    float2 v = ((const float2*)in)[i];
    __nv_bfloat162 h2 = __floats2bfloat162_rn(v.x, v.y);
    float r0 = v.x - __bfloat162float(h2.x);
    float r1 = v.y - __bfloat162float(h2.y);
    __nv_bfloat162 l2 = __floats2bfloat162_rn(r0, r1);
    hi[i] = *(uint32_t*)&h2;
    lo[i] = *(uint32_t*)&l2;
}

__global__ void split_w_kernel(const float* __restrict__ W,
                               uint32_t* __restrict__ hi, uint32_t* __restrict__ lo) {
    int i = blockIdx.x * blockDim.x + threadIdx.x;  // over 128*256
    if (i >= KP * D) return;
    int k2 = i >> 8;
    int n = i & 255;
    float x0 = W[(size_t)(2 * k2) * D + n];
    float x1 = W[(size_t)(2 * k2 + 1) * D + n];
    __nv_bfloat162 h2 = __floats2bfloat162_rn(x0, x1);
    float r0 = x0 - __bfloat162float(h2.x);
    float r1 = x1 - __bfloat162float(h2.y);
    __nv_bfloat162 l2 = __floats2bfloat162_rn(r0, r1);
    hi[i] = *(uint32_t*)&h2;
    lo[i] = *(uint32_t*)&l2;
}

// ---------------------------------------------------------------------------
// bf16 split tensor-core GEMM: C = Ah@Bh + Ah@Bl + Al@Bh  (fp32 accum)
// Block 128x128, 8 warps (warp tile 32x64), mma.sync m16n8k16.bf16.
// Double-buffered SMEM, 24 iterations = 3 phases x 8 k-tiles.
// ---------------------------------------------------------------------------
#define BM 128
#define BN 128
#define KW 16   // k2 words per tile (=32 k values)
#define ASTRIDE (KW + 4)   // 20 words: conflict-free
#define BSTRIDE (BN + 8)   // 136 words: conflict-free

__device__ __forceinline__ void mma_bf16(float* c, const uint32_t* a, const uint32_t* b) {
    asm volatile(
        "mma.sync.aligned.m16n8k16.row.col.f32.bf16.bf16.f32 "
        "{%0,%1,%2,%3}, {%4,%5,%6,%7}, {%8,%9}, {%0,%1,%2,%3};"
        : "+f"(c[0]), "+f"(c[1]), "+f"(c[2]), "+f"(c[3])
        : "r"(a[0]), "r"(a[1]), "r"(a[2]), "r"(a[3]), "r"(b[0]), "r"(b[1]));
}

__global__ __launch_bounds__(256) void bgemm_kernel(
    const uint32_t* __restrict__ Ah, const uint32_t* __restrict__ Al,
    const uint32_t* __restrict__ Bh, const uint32_t* __restrict__ Bl,
    float* __restrict__ C, int M) {
    __shared__ uint32_t As2[2][BM * ASTRIDE];
    __shared__ uint32_t Bs2[2][KW * BSTRIDE];

    const int tid = threadIdx.x;
    const int lane = tid & 31;
    const int wid = tid >> 5;
    const int warpM = wid & 3;          // 4 warps over 128 rows (32 each)
    const int warpN = wid >> 2;         // 2 warps over 128 cols (64 each)
    const int g = lane >> 2;
    const int t = lane & 3;
    const int rowBase = blockIdx.x * BM;
    const int colBase = blockIdx.y * BN;

    // A loader: 128 rows x 16 words = 512 uint4, 2/thread
    const int q0 = tid * 2, q1 = q0 + 1;
    const int ar0 = q0 >> 2, aw0 = (q0 & 3) << 2;
    const int ar1 = q1 >> 2, aw1 = (q1 & 3) << 2;
    const int grow0 = rowBase + ar0, grow1 = rowBase + ar1;
    // B loader: 16 rows x 128 words = 512 uint4, 2/thread
    const int bq0 = tid * 2, bq1 = bq0 + 1;
    const int br0 = bq0 >> 5, bw0 = (bq0 & 31) << 2;
    const int br1 = bq1 >> 5, bw1 = (bq1 & 31) << 2;

    const uint32_t* APtrs[3] = {Ah, Ah, Al};
    const uint32_t* BPtrs[3] = {Bh, Bl, Bh};

    float c[2][8][4];
#pragma unroll
    for (int mt = 0; mt < 2; mt++)
#pragma unroll
        for (int nt = 0; nt < 8; nt++)
#pragma unroll
            for (int r = 0; r < 4; r++) c[mt][nt][r] = 0.0f;

    uint4 pa0, pa1, pb0, pb1;
    {   // load iteration 0 (phase 0, kw0 = 0) and store to buffer 0
        const uint32_t* Ap = APtrs[0];
        const uint32_t* Bp = BPtrs[0];
        pa0 = (grow0 < M) ? *(const uint4*)(Ap + (size_t)grow0 * KP + aw0)
                          : make_uint4(0, 0, 0, 0);
        pa1 = (grow1 < M) ? *(const uint4*)(Ap + (size_t)grow1 * KP + aw1)
                          : make_uint4(0, 0, 0, 0);
        pb0 = *(const uint4*)(Bp + (size_t)br0 * D + colBase + bw0);
        pb1 = *(const uint4*)(Bp + (size_t)br1 * D + colBase + bw1);
        *(uint4*)&As2[0][ar0 * ASTRIDE + aw0] = pa0;
        *(uint4*)&As2[0][ar1 * ASTRIDE + aw1] = pa1;
        *(uint4*)&Bs2[0][br0 * BSTRIDE + bw0] = pb0;
        *(uint4*)&Bs2[0][br1 * BSTRIDE + bw1] = pb1;
    }
    __syncthreads();

    for (int it = 0; it < 24; it++) {
        const int cur = it & 1;
        const bool more = (it + 1 < 24);
        if (more) {
            int nx = it + 1;
            int p = nx >> 3;
            int kw0 = (nx & 7) * KW;
            const uint32_t* Ap = APtrs[p];
            const uint32_t* Bp = BPtrs[p];
            pa0 = (grow0 < M) ? *(const uint4*)(Ap + (size_t)grow0 * KP + kw0 + aw0)
                              : make_uint4(0, 0, 0, 0);
            pa1 = (grow1 < M) ? *(const uint4*)(Ap + (size_t)grow1 * KP + kw0 + aw1)
                              : make_uint4(0, 0, 0, 0);
            pb0 = *(const uint4*)(Bp + (size_t)(kw0 + br0) * D + colBase + bw0);
            pb1 = *(const uint4*)(Bp + (size_t)(kw0 + br1) * D + colBase + bw1);
        }

        const uint32_t* Asc = As2[cur];
        const uint32_t* Bsc = Bs2[cur];
#pragma unroll
        for (int ks = 0; ks < 2; ks++) {
            const int kb = ks * 8;
            uint32_t a[2][4], b[8][2];
#pragma unroll
            for (int mt = 0; mt < 2; mt++) {
                int m0 = warpM * 32 + mt * 16;
                a[mt][0] = Asc[(m0 + g) * ASTRIDE + kb + t];
                a[mt][1] = Asc[(m0 + g + 8) * ASTRIDE + kb + t];
                a[mt][2] = Asc[(m0 + g) * ASTRIDE + kb + t + 4];
                a[mt][3] = Asc[(m0 + g + 8) * ASTRIDE + kb + t + 4];
            }
#pragma unroll
            for (int nt = 0; nt < 8; nt++) {
                int n0 = warpN * 64 + nt * 8;
                b[nt][0] = Bsc[(kb + t) * BSTRIDE + n0 + g];
                b[nt][1] = Bsc[(kb + t + 4) * BSTRIDE + n0 + g];
            }
#pragma unroll
            for (int mt = 0; mt < 2; mt++)
#pragma unroll
                for (int nt = 0; nt < 8; nt++)
                    mma_bf16(c[mt][nt], a[mt], b[nt]);
        }

        if (more) {
            const int nxt = 1 - cur;
            *(uint4*)&As2[nxt][ar0 * ASTRIDE + aw0] = pa0;
            *(uint4*)&As2[nxt][ar1 * ASTRIDE + aw1] = pa1;
            *(uint4*)&Bs2[nxt][br0 * BSTRIDE + bw0] = pb0;
            *(uint4*)&Bs2[nxt][br1 * BSTRIDE + bw1] = pb1;
        }
        __syncthreads();
    }

    // Epilogue
#pragma unroll
    for (int mt = 0; mt < 2; mt++) {
#pragma unroll
        for (int nt = 0; nt < 8; nt++) {
            int row0 = rowBase + warpM * 32 + mt * 16 + g;
            int col = colBase + warpN * 64 + nt * 8 + t * 2;
            if (row0 < M)
                *(float2*)(C + (size_t)row0 * D + col) =
                    make_float2(c[mt][nt][0], c[mt][nt][1]);
            if (row0 + 8 < M)
                *(float2*)(C + (size_t)(row0 + 8) * D + col) =
                    make_float2(c[mt][nt][2], c[mt][nt][3]);
        }
    }
}

// ---------------------------------------------------------------------------
// Fused gather: warp-per-node.
// acc = h[n,:]*dinv^2 + sum_in-edges h[src,:]*w + b; relu.
// writePacked=1: emit bf16 hi/lo packed (feeds next GEMM). Else write fp32.
// ---------------------------------------------------------------------------
__global__ __launch_bounds__(256) void gather_kernel(
    const float* __restrict__ h,
    const int* __restrict__ rowstart,
    const int* __restrict__ csr_src,
    const float* __restrict__ csr_w,
    const float* __restrict__ dinv,
    const float* __restrict__ bias,
    float* __restrict__ out,
    uint32_t* __restrict__ outHi,
    uint32_t* __restrict__ outLo,
    int writePacked) {
    int node = (blockIdx.x * blockDim.x + threadIdx.x) >> 5;
    if (node >= N_NODES) return;
    int lane = threadIdx.x & 31;

    float dv = dinv[node];
    float w0 = dv * dv;
    const float4* selfp = (const float4*)(h + (size_t)node * D);
    float4 a0 = selfp[lane];
    float4 a1 = selfp[lane + 32];
    a0.x *= w0; a0.y *= w0; a0.z *= w0; a0.w *= w0;
    a1.x *= w0; a1.y *= w0; a1.z *= w0; a1.w *= w0;

    int beg = rowstart[node];
    int end = rowstart[node + 1];
    for (int j = beg; j < end; j++) {
        int s = __ldg(&csr_src[j]);
        float w = __ldg(&csr_w[j]);
        const float4* sp = (const float4*)(h + (size_t)s * D);
        float4 v0 = sp[lane];
        float4 v1 = sp[lane + 32];
        a0.x = fmaf(v0.x, w, a0.x); a0.y = fmaf(v0.y, w, a0.y);
        a0.z = fmaf(v0.z, w, a0.z); a0.w = fmaf(v0.w, w, a0.w);
        a1.x = fmaf(v1.x, w, a1.x); a1.y = fmaf(v1.y, w, a1.y);
        a1.z = fmaf(v1.z, w, a1.z); a1.w = fmaf(v1.w, w, a1.w);
    }

    const float4* b4 = (const float4*)bias;
    float4 bb0 = b4[lane];
    float4 bb1 = b4[lane + 32];
    a0.x = fmaxf(a0.x + bb0.x, 0.f); a0.y = fmaxf(a0.y + bb0.y, 0.f);
    a0.z = fmaxf(a0.z + bb0.z, 0.f); a0.w = fmaxf(a0.w + bb0.w, 0.f);
    a1.x = fmaxf(a1.x + bb1.x, 0.f); a1.y = fmaxf(a1.y + bb1.y, 0.f);
    a1.z = fmaxf(a1.z + bb1.z, 0.f); a1.w = fmaxf(a1.w + bb1.w, 0.f);

    if (writePacked) {
        // cols 4*lane..4*lane+3 -> k-pair words 2*lane, 2*lane+1 ; +128 cols -> +64 words
        size_t base = (size_t)node * KP;
        __nv_bfloat162 h00 = __floats2bfloat162_rn(a0.x, a0.y);
        __nv_bfloat162 h01 = __floats2bfloat162_rn(a0.z, a0.w);
        __nv_bfloat162 h10 = __floats2bfloat162_rn(a1.x, a1.y);
        __nv_bfloat162 h11 = __floats2bfloat162_rn(a1.z, a1.w);
        __nv_bfloat162 l00 = __floats2bfloat162_rn(a0.x - __bfloat162float(h00.x),
                                                   a0.y - __bfloat162float(h00.y));
        __nv_bfloat162 l01 = __floats2bfloat162_rn(a0.z - __bfloat162float(h01.x),
                                                   a0.w - __bfloat162float(h01.y));
        __nv_bfloat162 l10 = __floats2bfloat162_rn(a1.x - __bfloat162float(h10.x),
                                                   a1.y - __bfloat162float(h10.y));
        __nv_bfloat162 l11 = __floats2bfloat162_rn(a1.z - __bfloat162float(h11.x),
                                                   a1.w - __bfloat162float(h11.y));
        *(uint2*)&outHi[base + 2 * lane] = make_uint2(*(uint32_t*)&h00, *(uint32_t*)&h01);
        *(uint2*)&outHi[base + 64 + 2 * lane] = make_uint2(*(uint32_t*)&h10, *(uint32_t*)&h11);
        *(uint2*)&outLo[base + 2 * lane] = make_uint2(*(uint32_t*)&l00, *(uint32_t*)&l01);
        *(uint2*)&outLo[base + 64 + 2 * lane] = make_uint2(*(uint32_t*)&l10, *(uint32_t*)&l11);
    } else {
        float4* op = (float4*)(out + (size_t)node * D);
        op[lane] = a0;
        op[lane + 32] = a1;
    }
}

// ---------------------------------------------------------------------------
// Launch
// ---------------------------------------------------------------------------
extern "C" void kernel_launch(void* const* d_in, const int* in_sizes, int n_in,
                              void* d_out, int out_size) {
    const float* x = (const float*)d_in[0];
    const void* ei = d_in[1];
    const float* W1 = (const float*)d_in[2];
    const float* b1 = (const float*)d_in[3];
    const float* W2 = (const float*)d_in[4];
    const float* b2 = (const float*)d_in[5];
    float* out = (float*)d_out;

    float *h, *dinv, *csr_w;
    int *srcI, *dstI, *cnt, *cursor, *rowstart, *csr_src;
    uint32_t *ah, *al, *w1h, *w1l, *w2h, *w2l;
    cudaGetSymbolAddress((void**)&h, g_h);
    cudaGetSymbolAddress((void**)&dinv, g_dinv);
    cudaGetSymbolAddress((void**)&cnt, g_cnt);
    cudaGetSymbolAddress((void**)&cursor, g_cursor);
    cudaGetSymbolAddress((void**)&rowstart, g_rowstart);
    cudaGetSymbolAddress((void**)&csr_src, g_csr_src);
    cudaGetSymbolAddress((void**)&csr_w, g_csr_w);
    cudaGetSymbolAddress((void**)&srcI, g_src);
    cudaGetSymbolAddress((void**)&dstI, g_dst);
    cudaGetSymbolAddress((void**)&ah, g_ah);
    cudaGetSymbolAddress((void**)&al, g_al);
    cudaGetSymbolAddress((void**)&w1h, g_w1h);
    cudaGetSymbolAddress((void**)&w1l, g_w1l);
    cudaGetSymbolAddress((void**)&w2h, g_w2h);
    cudaGetSymbolAddress((void**)&w2l, g_w2l);

    const int TPB = 256;
    const int gN = (N_NODES + TPB - 1) / TPB;
    const int gE = (N_EDGES + TPB - 1) / TPB;
    const int gGather = (int)(((long long)N_NODES * 32 + TPB - 1) / TPB);
    const int nPairsA = N_NODES * KP;
    const int gSplitA = (nPairsA + TPB - 1) / TPB;
    const int gSplitW = (KP * D + TPB - 1) / TPB;
    dim3 gGemm((N_NODES + BM - 1) / BM, D / BN);   // (391, 2)

    // ---- prep: decode indices, CSR, weight/input splits ----
    detect_idx_kernel<<<1, 32>>>((const unsigned int*)ei);
    convert_idx_kernel<<<gE, TPB>>>(ei, srcI, dstI);
    zero_cnt_kernel<<<gN, TPB>>>(cnt, cursor);
    count_kernel<<<gE, TPB>>>(dstI, cnt);
    scan_kernel<<<1, 1024>>>(cnt, rowstart);
    dinv_kernel<<<gN, TPB>>>(cnt, dinv);
    fill_kernel<<<gE, TPB>>>(srcI, dstI, rowstart, cursor, dinv, csr_src, csr_w);
    split_w_kernel<<<gSplitW, TPB>>>(W1, w1h, w1l);
    split_w_kernel<<<gSplitW, TPB>>>(W2, w2h, w2l);
    split_rowmajor_kernel<<<gSplitA, TPB>>>(x, ah, al, nPairsA);

    // ---- layer 1 ----
    bgemm_kernel<<<gGemm, TPB>>>(ah, al, w1h, w1l, h, N_NODES);
    gather_kernel<<<gGather, TPB>>>(h, rowstart, csr_src, csr_w, dinv, b1,
                                    (float*)nullptr, ah, al, 1);

    // ---- layer 2 ----
    bgemm_kernel<<<gGemm, TPB>>>(ah, al, w2h, w2l, h, N_NODES);
    gather_kernel<<<gGather, TPB>>>(h, rowstart, csr_src, csr_w, dinv, b2,
                                    out, (uint32_t*)nullptr, (uint32_t*)nullptr, 0);
}